// round 14
// baseline (speedup 1.0000x reference)
#include <cuda_runtime.h>
#include <cuda_fp16.h>
#include <cstddef>
#include <cstdint>

#define N_NODES 14
#define BATCH   4096
#define FIN     1024
#define FOUT    1024
#define HID     512
#define MROWS   (BATCH * N_NODES)        /* 57344 */

#define SZ_FINAL (MROWS * FOUT)
#define SZ_CORR  (BATCH * N_NODES * N_NODES)
#define OFF_CORR SZ_FINAL
#define OFF_H    (OFF_CORR + SZ_CORR)

#define WSCALE   256.0f
#define WSCALE_I (1.0f / 256.0f)

// ------------------------- device scratch -----------------------------------
__device__ __align__(256) __half g_wfc_h[1024 * 1024];
__device__ __align__(256) __half g_w1_h[512 * 1024];
__device__ __align__(256) __half g_w2_h[1024 * 512];
__device__ __align__(256) __half g_pre16[2u * MROWS * HID];  // fp16 stacked [pre1 ; pre3]
__device__ float  g_A1n[196];
__device__ float  g_A2n[196];
__device__ float  g_xw1 [MROWS * HID];
__device__ float  g_xw2[2u * MROWS * FOUT];   // stacked [from pre1 ; from pre3]
__device__ float  g_corrn[BATCH * 196];
__device__ double g_part[4 * BATCH * 14 * 2];
__device__ float  g_scale[4][14];
__device__ float  g_shift[4][14];
__device__ unsigned int g_cnt1 = 0;
__device__ unsigned int g_cnt2 = 0;

__device__ __forceinline__ float lrelu(float v) { return v > 0.f ? v : 0.2f * v; }

__device__ __forceinline__ float wred(float v) {
#pragma unroll
    for (int o = 16; o; o >>= 1) v += __shfl_xor_sync(0xffffffffu, v, o);
    return v;
}

// ---- shared bn finalization (identical math to old bn_reduce_kernel) --------
// chunk: shared buffer of >= 56*32 doubles. NT = threads in block.
__device__ __forceinline__ void bn_finalize(
    double* chunk, int NT, int tid,
    int setA, int setB, const float* gA, const float* bA,
    const float* gB, const float* bB, double invCount) {
    for (int task = tid; task < 1792; task += NT) {
        int series = task >> 5, ch = task & 31;
        int set = (series < 28) ? setA : setB;
        int rem = series % 28;
        int node = rem >> 1, st = rem & 1;
        double s = 0;
        int b0 = ch * 128;
        for (int bb = 0; bb < 128; bb++)
            s += g_part[(((size_t)set * BATCH + b0 + bb) * 14 + node) * 2 + st];
        chunk[series * 32 + ch] = s;
    }
    __syncthreads();
    if (tid < 28) {
        int setidx = tid / 14, node = tid % 14;
        int set = setidx ? setB : setA;
        double S = 0, Q = 0;
        for (int ch = 0; ch < 32; ch++) {
            S += chunk[(setidx * 28 + node * 2 + 0) * 32 + ch];
            Q += chunk[(setidx * 28 + node * 2 + 1) * 32 + ch];
        }
        double mean = S * invCount;
        double var = Q * invCount - mean * mean;
        const float* g = setidx ? gB : gA;
        const float* be = setidx ? bB : bA;
        double sc = (double)g[node] / sqrt(var + 1e-5);
        g_scale[set][node] = (float)sc;
        g_shift[set][node] = (float)((double)be[node] - mean * sc);
    }
}

// ------------------------- fused prep: weight splits + adjacency -------------
// blocks [0,4096): fc_w ; [4096,6144): g1w ; [6144,8192): g2w ; 8192: adj prep
__global__ void prep_all(const float* __restrict__ fcw, const float* __restrict__ w1,
                         const float* __restrict__ w2, const float* __restrict__ adj1,
                         const float* __restrict__ adj2) {
    const int b = blockIdx.x, tid = threadIdx.x;
    if (b < 8192) {
        const float* W; __half* th; int K, Nw, idx;
        if (b < 4096)      { W = fcw; th = g_wfc_h; K = 1024; Nw = 1024; idx = b * 256 + tid; }
        else if (b < 6144) { W = w1;  th = g_w1_h;  K = 1024; Nw = 512;  idx = (b - 4096) * 256 + tid; }
        else               { W = w2;  th = g_w2_h;  K = 512;  Nw = 1024; idx = (b - 6144) * 256 + tid; }
        if (idx < K * Nw) {
            int n = idx / K, k = idx % K;
            th[idx] = __float2half(W[(size_t)k * Nw + n] * WSCALE);
        }
        return;
    }
    // adjacency prep (one block, 256 threads; active lanes < 196)
    __shared__ float a[2][196];
    __shared__ float dv[2][14];
    int t = tid;
    if (t < 196) {
        int i = t / 14, j = t % 14;
        a[0][t] = (i == j) ? 1.f : adj1[t];
        a[1][t] = (i == j) ? 1.f : adj2[t];
    }
    __syncthreads();
    if (t < 28) {
        int s = t / 14, r = t % 14;
        float acc = 0.f;
        for (int c = 0; c < 14; c++) acc += a[s][r * 14 + c];
        dv[s][r] = 1.f / sqrtf(fmaxf(acc, 1.f));
    }
    __syncthreads();
    if (t < 196) {
        int i = t / 14, j = t % 14;
        g_A1n[t] = dv[0][i] * a[0][t] * dv[0][j];
        g_A2n[t] = dv[1][i] * a[1][t] * dv[1][j];
    }
}

// ------------------------- fp16 tensor-core GEMM -----------------------------
__device__ __forceinline__ void cpa16(uint32_t dst, const void* src) {
    asm volatile("cp.async.cg.shared.global [%0], [%1], 16;\n" :: "r"(dst), "l"(src));
}
__device__ __forceinline__ void ldm_x4(uint32_t& r0, uint32_t& r1, uint32_t& r2, uint32_t& r3, uint32_t a) {
    asm volatile("ldmatrix.sync.aligned.m8n8.x4.shared.b16 {%0,%1,%2,%3},[%4];\n"
                 : "=r"(r0), "=r"(r1), "=r"(r2), "=r"(r3) : "r"(a));
}
__device__ __forceinline__ void mma_f16(float* c, const uint32_t* a, uint32_t b0, uint32_t b1) {
    asm volatile("mma.sync.aligned.m16n8k16.row.col.f32.f16.f16.f32 "
                 "{%0,%1,%2,%3},{%4,%5,%6,%7},{%8,%9},{%0,%1,%2,%3};\n"
                 : "+f"(c[0]), "+f"(c[1]), "+f"(c[2]), "+f"(c[3])
                 : "r"(a[0]), "r"(a[1]), "r"(a[2]), "r"(a[3]), "r"(b0), "r"(b1));
}

#define SPITCH 40                        /* halves: 80B rows, odd 16B stride */
#define A_SZ   (128 * SPITCH * 2)        /* 10240 B */
#define B_SZ   (256 * SPITCH * 2)        /* 20480 B */
#define STG    (A_SZ + B_SZ)             /* 30720 B per stage */
#define SM1    (2 * STG)                 /* 61440 B */

// C[M x NTOT] = op(A) @ (B16/256)^T ; B16 [NTOT][KTOT] fp16.
// AHALF: A is fp16 [M][KTOT]; else fp32.
// BN: A -> lrelu(a*scale[preset][row%14]+shift) before fp16 convert.
// STACKED: grid.y = 896; by>=448 -> second A/C stack, preset+1.
template <int KTOT, int NTOT, bool BN, bool EPI, bool AHALF, bool STACKED>
__global__ __launch_bounds__(256)
void hgemm2_k(const void* __restrict__ Ap, const __half* __restrict__ B16,
              const float* __restrict__ bias, float* __restrict__ C, int preset) {
    extern __shared__ char dsm[];
    const uint32_t sbase = (uint32_t)__cvta_generic_to_shared(dsm);
    const int tid = threadIdx.x, lane = tid & 31, wid = tid >> 5;
    const int bx = blockIdx.x;
    int by = blockIdx.y;
    const int wm = wid & 3, wn = wid >> 2;

    const char* Ab = (const char*)Ap;
    if (STACKED && by >= 448) {
        by -= 448;
        preset += 1;
        Ab += (size_t)MROWS * KTOT * (AHALF ? 2 : 4);
        C += (size_t)MROWS * NTOT;
    }

    const int ar = tid >> 3, ac4 = tid & 7;

    float psc[4], psh[4];
    if (BN) {
#pragma unroll
        for (int q = 0; q < 4; q++) {
            int node = (by * 128 + ar + q * 32) % N_NODES;
            psc[q] = g_scale[preset][node];
            psh[q] = g_shift[preset][node];
        }
    }

    float acc[2][16][4];
#pragma unroll
    for (int i = 0; i < 2; i++)
#pragma unroll
        for (int j = 0; j < 16; j++)
#pragma unroll
            for (int q = 0; q < 4; q++) acc[i][j][q] = 0.f;

    const int NK = KTOT / 32;

    float4 avf[4];
    uint2  avh[4];

#define LOAD_A(KT) do {                                                        \
        if constexpr (AHALF) {                                                 \
            const __half* Ah_ = (const __half*)Ab;                             \
            _Pragma("unroll")                                                  \
            for (int q_ = 0; q_ < 4; q_++)                                     \
                avh[q_] = *(const uint2*)(Ah_ +                                \
                    (size_t)(by * 128 + ar + q_ * 32) * KTOT + (KT) * 32 + ac4 * 4); \
        } else {                                                               \
            const float* Af_ = (const float*)Ab;                               \
            _Pragma("unroll")                                                  \
            for (int q_ = 0; q_ < 4; q_++)                                     \
                avf[q_] = *(const float4*)(Af_ +                               \
                    (size_t)(by * 128 + ar + q_ * 32) * KTOT + (KT) * 32 + ac4 * 4); \
        }                                                                      \
    } while (0)

#define STORE_A(S) do {                                                        \
        char* sd_ = dsm + (S) * STG;                                           \
        _Pragma("unroll")                                                      \
        for (int q_ = 0; q_ < 4; q_++) {                                       \
            float x0_, x1_, x2_, x3_;                                          \
            if constexpr (AHALF) {                                             \
                __half2 h0_ = ((const __half2*)&avh[q_])[0];                   \
                __half2 h1_ = ((const __half2*)&avh[q_])[1];                   \
                x0_ = __low2float(h0_); x1_ = __high2float(h0_);               \
                x2_ = __low2float(h1_); x3_ = __high2float(h1_);               \
            } else {                                                           \
                x0_ = avf[q_].x; x1_ = avf[q_].y;                              \
                x2_ = avf[q_].z; x3_ = avf[q_].w;                              \
            }                                                                  \
            if (BN) {                                                          \
                x0_ = lrelu(fmaf(x0_, psc[q_], psh[q_]));                      \
                x1_ = lrelu(fmaf(x1_, psc[q_], psh[q_]));                      \
                x2_ = lrelu(fmaf(x2_, psc[q_], psh[q_]));                      \
                x3_ = lrelu(fmaf(x3_, psc[q_], psh[q_]));                      \
            }                                                                  \
            __half2 p0_ = __floats2half2_rn(x0_, x1_);                         \
            __half2 p1_ = __floats2half2_rn(x2_, x3_);                         \
            uint2 pk_;                                                         \
            pk_.x = *(uint32_t*)&p0_;                                          \
            pk_.y = *(uint32_t*)&p1_;                                          \
            *(uint2*)(sd_ + (ar + q_ * 32) * 80 + ac4 * 8) = pk_;              \
        }                                                                      \
    } while (0)

#define FILL_B(KT, S) do {                                                     \
        const uint32_t sb_ = sbase + (S) * STG + A_SZ;                         \
        const int k0_ = (KT) * 32;                                             \
        _Pragma("unroll")                                                      \
        for (int q_ = 0; q_ < 4; q_++) {                                       \
            int idx = tid + q_ * 256;                                          \
            int r = (idx >> 2) & 255, c = idx & 3;                             \
            cpa16(sb_ + r * 80u + c * 16u,                                     \
                  B16 + (size_t)(bx * 256 + r) * KTOT + k0_ + c * 8);          \
        }                                                                      \
        asm volatile("cp.async.commit_group;\n");                              \
    } while (0)

    {
        LOAD_A(0);
        FILL_B(0, 0);
        STORE_A(0);
    }

    for (int kt = 0; kt < NK; kt++) {
        const bool hasNext = (kt + 1 < NK);
        if (hasNext) {
            LOAD_A(kt + 1);
            FILL_B(kt + 1, (kt + 1) & 1);
            asm volatile("cp.async.wait_group 1;\n");
        } else {
            asm volatile("cp.async.wait_group 0;\n");
        }
        __syncthreads();

        const uint32_t st = sbase + (kt & 1) * STG;
        const uint32_t stA = st, stB = st + A_SZ;
#pragma unroll
        for (int khalf = 0; khalf < 32; khalf += 16) {
            uint32_t ah[2][4];
#pragma unroll
            for (int ms = 0; ms < 2; ms++) {
                int row  = wm * 32 + ms * 16 + ((lane >> 3) & 1) * 8 + (lane & 7);
                int kcol = khalf + (lane >> 4) * 8;
                uint32_t off = (uint32_t)(row * SPITCH + kcol) * 2;
                ldm_x4(ah[ms][0], ah[ms][1], ah[ms][2], ah[ms][3], stA + off);
            }
#pragma unroll
            for (int np = 0; np < 8; np++) {
                int nrow = wn * 128 + np * 16 + (lane >> 4) * 8 + (lane & 7);
                int kcol = khalf + ((lane >> 3) & 1) * 8;
                uint32_t off = (uint32_t)(nrow * SPITCH + kcol) * 2;
                uint32_t bh[4];
                ldm_x4(bh[0], bh[1], bh[2], bh[3], stB + off);
#pragma unroll
                for (int ms = 0; ms < 2; ms++)
#pragma unroll
                    for (int q = 0; q < 2; q++)
                        mma_f16(acc[ms][np * 2 + q], ah[ms], bh[2 * q], bh[2 * q + 1]);
            }
        }
        if (hasNext) STORE_A((kt + 1) & 1);
        __syncthreads();
    }
#undef FILL_B
#undef STORE_A
#undef LOAD_A

    // epilogue (unscale by 1/256, then optional bias+lrelu)
    const int rbase = by * 128 + wm * 32;
    const int cbase = bx * 256 + wn * 128;
    const int rq = lane >> 2, cq = (lane & 3) * 2;
#pragma unroll
    for (int ms = 0; ms < 2; ms++)
#pragma unroll
        for (int ns = 0; ns < 16; ns++) {
            int r0  = rbase + ms * 16 + rq;
            int col = cbase + ns * 8 + cq;
            float v0 = acc[ms][ns][0] * WSCALE_I, v1 = acc[ms][ns][1] * WSCALE_I;
            float v2 = acc[ms][ns][2] * WSCALE_I, v3 = acc[ms][ns][3] * WSCALE_I;
            if (EPI) {
                float b0 = bias[col], b1 = bias[col + 1];
                v0 = lrelu(v0 + b0); v1 = lrelu(v1 + b1);
                v2 = lrelu(v2 + b0); v3 = lrelu(v3 + b1);
            }
            *(float2*)&C[(size_t)r0 * NTOT + col]       = make_float2(v0, v1);
            *(float2*)&C[(size_t)(r0 + 8) * NTOT + col] = make_float2(v2, v3);
        }
}

// ------------------------- correlation kernel (smem-staged) ------------------
__global__ __launch_bounds__(256) void corr_kernel(const float* __restrict__ h,
                                                   float* __restrict__ corr_out) {
    extern __shared__ float4 hs4[];      // 14 rows x 256 float4 = 57344 B
    __shared__ float rn[14];
    __shared__ float cmat[196];
    __shared__ float dd[14];

    const int b = blockIdx.x;
    const int tid = threadIdx.x, lane = tid & 31, warp = tid >> 5;
    const float4* hb4 = (const float4*)(h + (size_t)b * 14336);

#pragma unroll
    for (int q = 0; q < 14; q++) hs4[tid + q * 256] = hb4[tid + q * 256];
    __syncthreads();

#pragma unroll 1
    for (int pass = 0; pass < 2; pass++) {
        int i = pass * 8 + warp;
        if (i < 14) {
            float4 ri[8];
#pragma unroll
            for (int k = 0; k < 8; k++) ri[k] = hs4[i * 256 + lane + 32 * k];
            float s = 0.f;
#pragma unroll
            for (int k = 0; k < 8; k++) {
                s = fmaf(ri[k].x, ri[k].x, s);
                s = fmaf(ri[k].y, ri[k].y, s);
                s = fmaf(ri[k].z, ri[k].z, s);
                s = fmaf(ri[k].w, ri[k].w, s);
            }
            s = wred(s);
            if (!lane) rn[i] = rsqrtf(fmaxf(s, 1e-16f));
#pragma unroll 1
            for (int j = i + 1; j < 14; j++) {
                float sj = 0.f;
#pragma unroll
                for (int k = 0; k < 8; k++) {
                    float4 vj = hs4[j * 256 + lane + 32 * k];
                    sj = fmaf(ri[k].x, vj.x, sj);
                    sj = fmaf(ri[k].y, vj.y, sj);
                    sj = fmaf(ri[k].z, vj.z, sj);
                    sj = fmaf(ri[k].w, vj.w, sj);
                }
                sj = wred(sj);
                if (!lane) cmat[i * 14 + j] = sj;
            }
        }
    }
    __syncthreads();

    float val = 0.f;
    if (tid < 196) {
        int i = tid / 14, j = tid % 14;
        if (i == j) val = 1.f;
        else {
            int lo = i < j ? i : j, hi = i < j ? j : i;
            val = fabsf(cmat[lo * 14 + hi] * rn[i] * rn[j]);
        }
    }
    __syncthreads();
    if (tid < 196) cmat[tid] = val;
    __syncthreads();
    if (tid < 14) {
        float s = 0.f;
        for (int j = 0; j < 14; j++) s += cmat[tid * 14 + j];
        dd[tid] = 1.f / sqrtf(fmaxf(s, 1.f));
    }
    __syncthreads();
    if (tid < 196) {
        int i = tid / 14, j = tid % 14;
        corr_out[(size_t)b * 196 + tid] = cmat[tid];
        g_corrn[(size_t)b * 196 + tid] = dd[i] * cmat[tid] * dd[j];
    }
}

// ------------------------- branch-1 aggregation + BN stats + fused reduce ----
__global__ __launch_bounds__(128) void agg1_kernel(
    const float* __restrict__ b1,
    const float* __restrict__ gamma1, const float* __restrict__ beta1,
    const float* __restrict__ gamma3, const float* __restrict__ beta3) {
    const int b = blockIdx.x, tid = threadIdx.x, lane = tid & 31, warp = tid >> 5;
    __shared__ __align__(8) float sh[14 * 512];
    __shared__ float sA1[196], sA2[196];
    __shared__ float red[4][14][4];
    __shared__ bool isLast;
    for (int t = tid; t < 196; t += 128) { sA1[t] = g_A1n[t]; sA2[t] = g_A2n[t]; }
    const float4* src = (const float4*)(g_xw1 + (size_t)b * 7168);
    float4* d4 = (float4*)sh;
#pragma unroll
    for (int k = 0; k < 14; k++) d4[tid + k * 128] = src[tid + k * 128];
    __syncthreads();
    float biasv[4];
#pragma unroll
    for (int t = 0; t < 4; t++) biasv[t] = b1[tid + t * 128];
    __half* p1 = g_pre16 + (size_t)b * 7168;
    __half* p3 = g_pre16 + (size_t)MROWS * 512 + (size_t)b * 7168;
#pragma unroll 1
    for (int i = 0; i < 14; i++) {
        float w1[14], w2[14];
#pragma unroll
        for (int j = 0; j < 14; j++) { w1[j] = sA1[i * 14 + j]; w2[j] = sA2[i * 14 + j]; }
        float s1 = 0, q1 = 0, s3 = 0, q3 = 0;
#pragma unroll
        for (int t = 0; t < 4; t++) {
            int c = tid + t * 128;
            float a1 = biasv[t], a3 = biasv[t];
#pragma unroll
            for (int j = 0; j < 14; j++) {
                float v = sh[j * 512 + c];
                a1 = fmaf(w1[j], v, a1);
                a3 = fmaf(w2[j], v, a3);
            }
            p1[i * 512 + c] = __float2half(a1);
            p3[i * 512 + c] = __float2half(a3);
            s1 += a1; q1 = fmaf(a1, a1, q1);
            s3 += a3; q3 = fmaf(a3, a3, q3);
        }
        s1 = wred(s1); q1 = wred(q1); s3 = wred(s3); q3 = wred(q3);
        if (!lane) { red[0][i][warp] = s1; red[1][i][warp] = q1; red[2][i][warp] = s3; red[3][i][warp] = q3; }
    }
    __syncthreads();
    if (tid < 28) {
        int node = tid % 14, st = tid / 14;
        double v1 = (double)red[st][node][0] + red[st][node][1] + red[st][node][2] + red[st][node][3];
        double v3 = (double)red[st + 2][node][0] + red[st + 2][node][1] + red[st + 2][node][2] + red[st + 2][node][3];
        g_part[(((size_t)0 * BATCH + b) * 14 + node) * 2 + st] = v1;
        g_part[(((size_t)1 * BATCH + b) * 14 + node) * 2 + st] = v3;
    }

    // last-block fused bn reduce (sets 0,1)
    __threadfence();
    __syncthreads();
    if (tid == 0) {
        unsigned v = atomicAdd(&g_cnt1, 1u);
        isLast = (v == BATCH - 1);
        if (isLast) g_cnt1 = 0;
    }
    __syncthreads();
    if (isLast) {
        bn_finalize((double*)sh, 128, tid, 0, 1, gamma1, beta1, gamma3, beta3,
                    1.0 / ((double)BATCH * HID));
    }
}

// ------------------------- branch-2 aggregation (stats / write) --------------
template <bool WRITE>
__global__ __launch_bounds__(256) void agg2_kernel(
    const float* __restrict__ b2,
    const float* __restrict__ gamma2, const float* __restrict__ beta2,
    float* __restrict__ out) {
    const int b = blockIdx.x, tid = threadIdx.x, lane = tid & 31, warp = tid >> 5;
    __shared__ float sadj[196];
    __shared__ float sscale[2][14], sshift[2][14];
    __shared__ float red[4][14][8];
    __shared__ __align__(8) double chunk2[56 * 32];
    __shared__ bool isLast;
    if (tid < 196) sadj[tid] = g_corrn[(size_t)b * 196 + tid];
    if (WRITE && tid < 28) {
        int s = tid / 14, n = tid % 14;
        sscale[s][n] = g_scale[2 + s][n];
        sshift[s][n] = g_shift[2 + s][n];
    }
    __syncthreads();
    const float* xb = g_xw2 + (size_t)b * 14336;
    const float* xa = g_xw2 + (size_t)MROWS * 1024 + (size_t)b * 14336;

    float s2a[14], q2a[14], s4a[14], q4a[14];
    if (!WRITE) {
#pragma unroll
        for (int i = 0; i < 14; i++) { s2a[i] = 0; q2a[i] = 0; s4a[i] = 0; q4a[i] = 0; }
    }

#pragma unroll 1
    for (int t = 0; t < 4; t++) {
        const int c = tid + t * 256;
        float v2r[14], v4r[14];
#pragma unroll
        for (int j = 0; j < 14; j++) {
            v2r[j] = __ldg(xb + j * 1024 + c);
            v4r[j] = __ldg(xa + j * 1024 + c);
        }
        const float bv = __ldg(b2 + c);
#pragma unroll
        for (int i = 0; i < 14; i++) {
            float a2 = bv, a4 = bv;
#pragma unroll
            for (int j = 0; j < 14; j++) {
                float w = sadj[i * 14 + j];
                a2 = fmaf(w, v2r[j], a2);
                a4 = fmaf(w, v4r[j], a4);
            }
            if (WRITE) {
                out[((size_t)b * 14 + i) * 1024 + c] =
                    lrelu(fmaf(a2, sscale[0][i], sshift[0][i])) +
                    lrelu(fmaf(a4, sscale[1][i], sshift[1][i]));
            } else {
                s2a[i] += a2; q2a[i] = fmaf(a2, a2, q2a[i]);
                s4a[i] += a4; q4a[i] = fmaf(a4, a4, q4a[i]);
            }
        }
    }

    if (!WRITE) {
#pragma unroll 1
        for (int i = 0; i < 14; i++) {
            float s2 = wred(s2a[i]), q2 = wred(q2a[i]);
            float s4 = wred(s4a[i]), q4 = wred(q4a[i]);
            if (!lane) { red[0][i][warp] = s2; red[1][i][warp] = q2; red[2][i][warp] = s4; red[3][i][warp] = q4; }
        }
        __syncthreads();
        if (tid < 28) {
            int node = tid % 14, st = tid / 14;
            double v2 = 0, v4 = 0;
#pragma unroll
            for (int wq = 0; wq < 8; wq++) {
                v2 += (double)red[st][node][wq];
                v4 += (double)red[st + 2][node][wq];
            }
            g_part[(((size_t)2 * BATCH + b) * 14 + node) * 2 + st] = v2;
            g_part[(((size_t)3 * BATCH + b) * 14 + node) * 2 + st] = v4;
        }

        // last-block fused bn reduce (sets 2,3 — both gamma2/beta2)
        __threadfence();
        __syncthreads();
        if (tid == 0) {
            unsigned v = atomicAdd(&g_cnt2, 1u);
            isLast = (v == BATCH - 1);
            if (isLast) g_cnt2 = 0;
        }
        __syncthreads();
        if (isLast) {
            bn_finalize(chunk2, 256, tid, 2, 3, gamma2, beta2, gamma2, beta2,
                        1.0 / ((double)BATCH * FOUT));
        }
    }
}

// ------------------------- host launcher -------------------------------------
static void* sym_addr(const void* sym) {
    void* p = nullptr;
    cudaGetSymbolAddress(&p, sym);
    return p;
}

extern "C" void kernel_launch(void* const* d_in, const int* in_sizes, int n_in,
                              void* d_out, int out_size) {
    const float* x     = (const float*)d_in[0];
    const float* adj1  = (const float*)d_in[1];
    const float* adj2  = (const float*)d_in[2];
    const float* fc_w  = (const float*)d_in[3];
    const float* fc_b  = (const float*)d_in[4];
    const float* g1w   = (const float*)d_in[5];
    const float* g1b   = (const float*)d_in[6];
    const float* g2w   = (const float*)d_in[7];
    const float* g2b   = (const float*)d_in[8];
    const float* gamma1 = (const float*)d_in[9];
    const float* beta1  = (const float*)d_in[10];
    const float* gamma2 = (const float*)d_in[11];
    const float* beta2  = (const float*)d_in[12];
    const float* gamma3 = (const float*)d_in[13];
    const float* beta3  = (const float*)d_in[14];

    float* out      = (float*)d_out;
    float* corr_out = out + OFF_CORR;
    float* h_out    = out + OFF_H;

    __half* p_wfch  = (__half*)sym_addr(g_wfc_h);
    __half* p_w1h   = (__half*)sym_addr(g_w1_h);
    __half* p_w2h   = (__half*)sym_addr(g_w2_h);
    __half* p_pre16 = (__half*)sym_addr(g_pre16);
    float*  p_xw1   = (float*)sym_addr(g_xw1);
    float*  p_xw2   = (float*)sym_addr(g_xw2);

    const int CORR_SM = 14 * 1024 * 4;       // 57344

    static cudaStream_t s1 = nullptr;
    static cudaEvent_t eFork = nullptr, eJoin = nullptr;
    if (!s1) {
        cudaStreamCreateWithFlags(&s1, cudaStreamNonBlocking);
        cudaEventCreateWithFlags(&eFork, cudaEventDisableTiming);
        cudaEventCreateWithFlags(&eJoin, cudaEventDisableTiming);
        cudaFuncSetAttribute(hgemm2_k<1024, 1024, false, true,  false, false>, cudaFuncAttributeMaxDynamicSharedMemorySize, SM1);
        cudaFuncSetAttribute(hgemm2_k<1024,  512, false, false, false, false>, cudaFuncAttributeMaxDynamicSharedMemorySize, SM1);
        cudaFuncSetAttribute(hgemm2_k< 512, 1024, true,  false, true,  true >, cudaFuncAttributeMaxDynamicSharedMemorySize, SM1);
        cudaFuncSetAttribute(corr_kernel, cudaFuncAttributeMaxDynamicSharedMemorySize, CORR_SM);
    }

    // 1) fused prep: all weight splits + adjacency normalize
    prep_all<<<8193, 256>>>(fc_w, g1w, g2w, adj1, adj2);

    // ---- fork: chain A (fc GEMM -> corr) on s1 ----
    cudaEventRecord(eFork, 0);
    cudaStreamWaitEvent(s1, eFork, 0);

    hgemm2_k<1024, 1024, false, true, false, false><<<dim3(4, 448), 256, SM1, s1>>>(x, p_wfch, fc_b, h_out, 0);
    corr_kernel<<<BATCH, 256, CORR_SM, s1>>>(h_out, corr_out);
    cudaEventRecord(eJoin, s1);

    // ---- chain B (gcn1 -> agg1(+bn1) -> gcn2) on the main stream ----
    hgemm2_k<1024, 512, false, false, false, false><<<dim3(2, 448), 256, SM1>>>(x, p_w1h, nullptr, p_xw1, 0);
    agg1_kernel<<<BATCH, 128>>>(g1b, gamma1, beta1, gamma3, beta3);

    // stacked gcn2 GEMM: by<448 -> pre1/preset0, by>=448 -> pre3/preset1 (A fp16)
    hgemm2_k<512, 1024, true, false, true, true><<<dim3(4, 896), 256, SM1>>>(p_pre16, p_w2h, nullptr, p_xw2, 0);

    // ---- join: agg2 needs corrn (chain A) + xw2 (chain B) ----
    cudaStreamWaitEvent(0, eJoin, 0);

    agg2_kernel<false><<<BATCH, 256>>>(g2b, gamma2, beta2, nullptr);
    agg2_kernel<true><<<BATCH, 256>>>(g2b, gamma2, beta2, out);

    (void)in_sizes; (void)n_in; (void)out_size;
}

// round 15
// speedup vs baseline: 1.0965x; 1.0965x over previous
#include <cuda_runtime.h>
#include <cuda_fp16.h>
#include <cstddef>
#include <cstdint>

#define N_NODES 14
#define BATCH   4096
#define FIN     1024
#define FOUT    1024
#define HID     512
#define MROWS   (BATCH * N_NODES)        /* 57344 */

#define SZ_FINAL (MROWS * FOUT)
#define SZ_CORR  (BATCH * N_NODES * N_NODES)
#define OFF_CORR SZ_FINAL
#define OFF_H    (OFF_CORR + SZ_CORR)

#define WSCALE   256.0f
#define WSCALE_I (1.0f / 256.0f)

// ------------------------- device scratch -----------------------------------
__device__ __align__(256) __half g_wfc_h[1024 * 1024];
__device__ __align__(256) __half g_w1_h[512 * 1024];
__device__ __align__(256) __half g_w2_h[1024 * 512];
__device__ __align__(256) __half g_pre16[2u * MROWS * HID];  // fp16 stacked [pre1 ; pre3]
__device__ float  g_A1n[196];
__device__ float  g_A2n[196];
__device__ float  g_xw1 [MROWS * HID];
__device__ float  g_xw2[2u * MROWS * FOUT];   // stacked [from pre1 ; from pre3]
__device__ float  g_corrn[BATCH * 196];
__device__ double g_part[4 * BATCH * 14 * 2];
__device__ float  g_scale[4][14];
__device__ float  g_shift[4][14];
__device__ unsigned int g_cnt1 = 0;
__device__ unsigned int g_cnt2 = 0;

__device__ __forceinline__ float lrelu(float v) { return v > 0.f ? v : 0.2f * v; }

__device__ __forceinline__ float wred(float v) {
#pragma unroll
    for (int o = 16; o; o >>= 1) v += __shfl_xor_sync(0xffffffffu, v, o);
    return v;
}

// ---- shared bn finalization (identical math to old bn_reduce_kernel) --------
__device__ __forceinline__ void bn_finalize(
    double* chunk, int NT, int tid,
    int setA, int setB, const float* gA, const float* bA,
    const float* gB, const float* bB, double invCount) {
    for (int task = tid; task < 1792; task += NT) {
        int series = task >> 5, ch = task & 31;
        int set = (series < 28) ? setA : setB;
        int rem = series % 28;
        int node = rem >> 1, st = rem & 1;
        double s = 0;
        int b0 = ch * 128;
        for (int bb = 0; bb < 128; bb++)
            s += g_part[(((size_t)set * BATCH + b0 + bb) * 14 + node) * 2 + st];
        chunk[series * 32 + ch] = s;
    }
    __syncthreads();
    if (tid < 28) {
        int setidx = tid / 14, node = tid % 14;
        int set = setidx ? setB : setA;
        double S = 0, Q = 0;
        for (int ch = 0; ch < 32; ch++) {
            S += chunk[(setidx * 28 + node * 2 + 0) * 32 + ch];
            Q += chunk[(setidx * 28 + node * 2 + 1) * 32 + ch];
        }
        double mean = S * invCount;
        double var = Q * invCount - mean * mean;
        const float* g = setidx ? gB : gA;
        const float* be = setidx ? bB : bA;
        double sc = (double)g[node] / sqrt(var + 1e-5);
        g_scale[set][node] = (float)sc;
        g_shift[set][node] = (float)((double)be[node] - mean * sc);
    }
}

// ------------------------- fused prep: weight splits + adjacency -------------
__global__ void prep_all(const float* __restrict__ fcw, const float* __restrict__ w1,
                         const float* __restrict__ w2, const float* __restrict__ adj1,
                         const float* __restrict__ adj2) {
    const int b = blockIdx.x, tid = threadIdx.x;
    if (b < 8192) {
        const float* W; __half* th; int K, Nw, idx;
        if (b < 4096)      { W = fcw; th = g_wfc_h; K = 1024; Nw = 1024; idx = b * 256 + tid; }
        else if (b < 6144) { W = w1;  th = g_w1_h;  K = 1024; Nw = 512;  idx = (b - 4096) * 256 + tid; }
        else               { W = w2;  th = g_w2_h;  K = 512;  Nw = 1024; idx = (b - 6144) * 256 + tid; }
        if (idx < K * Nw) {
            int n = idx / K, k = idx % K;
            th[idx] = __float2half(W[(size_t)k * Nw + n] * WSCALE);
        }
        return;
    }
    __shared__ float a[2][196];
    __shared__ float dv[2][14];
    int t = tid;
    if (t < 196) {
        int i = t / 14, j = t % 14;
        a[0][t] = (i == j) ? 1.f : adj1[t];
        a[1][t] = (i == j) ? 1.f : adj2[t];
    }
    __syncthreads();
    if (t < 28) {
        int s = t / 14, r = t % 14;
        float acc = 0.f;
        for (int c = 0; c < 14; c++) acc += a[s][r * 14 + c];
        dv[s][r] = 1.f / sqrtf(fmaxf(acc, 1.f));
    }
    __syncthreads();
    if (t < 196) {
        int i = t / 14, j = t % 14;
        g_A1n[t] = dv[0][i] * a[0][t] * dv[0][j];
        g_A2n[t] = dv[1][i] * a[1][t] * dv[1][j];
    }
}

// ------------------------- fp16 tensor-core GEMM -----------------------------
__device__ __forceinline__ void cpa16(uint32_t dst, const void* src) {
    asm volatile("cp.async.cg.shared.global [%0], [%1], 16;\n" :: "r"(dst), "l"(src));
}
__device__ __forceinline__ void ldm_x4(uint32_t& r0, uint32_t& r1, uint32_t& r2, uint32_t& r3, uint32_t a) {
    asm volatile("ldmatrix.sync.aligned.m8n8.x4.shared.b16 {%0,%1,%2,%3},[%4];\n"
                 : "=r"(r0), "=r"(r1), "=r"(r2), "=r"(r3) : "r"(a));
}
__device__ __forceinline__ void mma_f16(float* c, const uint32_t* a, uint32_t b0, uint32_t b1) {
    asm volatile("mma.sync.aligned.m16n8k16.row.col.f32.f16.f16.f32 "
                 "{%0,%1,%2,%3},{%4,%5,%6,%7},{%8,%9},{%0,%1,%2,%3};\n"
                 : "+f"(c[0]), "+f"(c[1]), "+f"(c[2]), "+f"(c[3])
                 : "r"(a[0]), "r"(a[1]), "r"(a[2]), "r"(a[3]), "r"(b0), "r"(b1));
}

#define SPITCH 40                        /* halves: 80B rows, odd 16B stride */
#define A_SZ   (128 * SPITCH * 2)        /* 10240 B */
#define B_SZ   (128 * SPITCH * 2)        /* 10240 B (128-row B tile) */
#define STG    (A_SZ + B_SZ)             /* 20480 B per stage */
#define SM1    (2 * STG)                 /* 40960 B -> 2 CTAs/SM */

// C[M x NTOT] = op(A) @ (B16/256)^T ; B16 [NTOT][KTOT] fp16.
// Tile 128 x 128, 256 threads, warp tile 32 x 64, 2-stage pipeline, 2 CTAs/SM.
template <int KTOT, int NTOT, bool BN, bool EPI, bool AHALF, bool STACKED>
__global__ __launch_bounds__(256, 2)
void hgemm2_k(const void* __restrict__ Ap, const __half* __restrict__ B16,
              const float* __restrict__ bias, float* __restrict__ C, int preset) {
    extern __shared__ char dsm[];
    const uint32_t sbase = (uint32_t)__cvta_generic_to_shared(dsm);
    const int tid = threadIdx.x, lane = tid & 31, wid = tid >> 5;
    const int bx = blockIdx.x;
    int by = blockIdx.y;
    const int wm = wid & 3, wn = wid >> 2;

    const char* Ab = (const char*)Ap;
    if (STACKED && by >= 448) {
        by -= 448;
        preset += 1;
        Ab += (size_t)MROWS * KTOT * (AHALF ? 2 : 4);
        C += (size_t)MROWS * NTOT;
    }

    const int ar = tid >> 3, ac4 = tid & 7;

    float psc[4], psh[4];
    if (BN) {
#pragma unroll
        for (int q = 0; q < 4; q++) {
            int node = (by * 128 + ar + q * 32) % N_NODES;
            psc[q] = g_scale[preset][node];
            psh[q] = g_shift[preset][node];
        }
    }

    float acc[2][8][4];
#pragma unroll
    for (int i = 0; i < 2; i++)
#pragma unroll
        for (int j = 0; j < 8; j++)
#pragma unroll
            for (int q = 0; q < 4; q++) acc[i][j][q] = 0.f;

    const int NK = KTOT / 32;

    float4 avf[4];
    uint2  avh[4];

#define LOAD_A(KT) do {                                                        \
        if constexpr (AHALF) {                                                 \
            const __half* Ah_ = (const __half*)Ab;                             \
            _Pragma("unroll")                                                  \
            for (int q_ = 0; q_ < 4; q_++)                                     \
                avh[q_] = *(const uint2*)(Ah_ +                                \
                    (size_t)(by * 128 + ar + q_ * 32) * KTOT + (KT) * 32 + ac4 * 4); \
        } else {                                                               \
            const float* Af_ = (const float*)Ab;                               \
            _Pragma("unroll")                                                  \
            for (int q_ = 0; q_ < 4; q_++)                                     \
                avf[q_] = *(const float4*)(Af_ +                               \
                    (size_t)(by * 128 + ar + q_ * 32) * KTOT + (KT) * 32 + ac4 * 4); \
        }                                                                      \
    } while (0)

#define STORE_A(S) do {                                                        \
        char* sd_ = dsm + (S) * STG;                                           \
        _Pragma("unroll")                                                      \
        for (int q_ = 0; q_ < 4; q_++) {                                       \
            float x0_, x1_, x2_, x3_;                                          \
            if constexpr (AHALF) {                                             \
                __half2 h0_ = ((const __half2*)&avh[q_])[0];                   \
                __half2 h1_ = ((const __half2*)&avh[q_])[1];                   \
                x0_ = __low2float(h0_); x1_ = __high2float(h0_);               \
                x2_ = __low2float(h1_); x3_ = __high2float(h1_);               \
            } else {                                                           \
                x0_ = avf[q_].x; x1_ = avf[q_].y;                              \
                x2_ = avf[q_].z; x3_ = avf[q_].w;                              \
            }                                                                  \
            if (BN) {                                                          \
                x0_ = lrelu(fmaf(x0_, psc[q_], psh[q_]));                      \
                x1_ = lrelu(fmaf(x1_, psc[q_], psh[q_]));                      \
                x2_ = lrelu(fmaf(x2_, psc[q_], psh[q_]));                      \
                x3_ = lrelu(fmaf(x3_, psc[q_], psh[q_]));                      \
            }                                                                  \
            __half2 p0_ = __floats2half2_rn(x0_, x1_);                         \
            __half2 p1_ = __floats2half2_rn(x2_, x3_);                         \
            uint2 pk_;                                                         \
            pk_.x = *(uint32_t*)&p0_;                                          \
            pk_.y = *(uint32_t*)&p1_;                                          \
            *(uint2*)(sd_ + (ar + q_ * 32) * 80 + ac4 * 8) = pk_;              \
        }                                                                      \
    } while (0)

#define FILL_B(KT, S) do {                                                     \
        const uint32_t sb_ = sbase + (S) * STG + A_SZ;                         \
        const int k0_ = (KT) * 32;                                             \
        _Pragma("unroll")                                                      \
        for (int q_ = 0; q_ < 2; q_++) {                                       \
            int idx = tid + q_ * 256;                                          \
            int r = (idx >> 2) & 127, c = idx & 3;                             \
            cpa16(sb_ + r * 80u + c * 16u,                                     \
                  B16 + (size_t)(bx * 128 + r) * KTOT + k0_ + c * 8);          \
        }                                                                      \
        asm volatile("cp.async.commit_group;\n");                              \
    } while (0)

    {
        LOAD_A(0);
        FILL_B(0, 0);
        STORE_A(0);
    }

    for (int kt = 0; kt < NK; kt++) {
        const bool hasNext = (kt + 1 < NK);
        if (hasNext) {
            LOAD_A(kt + 1);
            FILL_B(kt + 1, (kt + 1) & 1);
            asm volatile("cp.async.wait_group 1;\n");
        } else {
            asm volatile("cp.async.wait_group 0;\n");
        }
        __syncthreads();

        const uint32_t st = sbase + (kt & 1) * STG;
        const uint32_t stA = st, stB = st + A_SZ;
#pragma unroll
        for (int khalf = 0; khalf < 32; khalf += 16) {
            uint32_t ah[2][4];
#pragma unroll
            for (int ms = 0; ms < 2; ms++) {
                int row  = wm * 32 + ms * 16 + ((lane >> 3) & 1) * 8 + (lane & 7);
                int kcol = khalf + (lane >> 4) * 8;
                uint32_t off = (uint32_t)(row * SPITCH + kcol) * 2;
                ldm_x4(ah[ms][0], ah[ms][1], ah[ms][2], ah[ms][3], stA + off);
            }
#pragma unroll
            for (int np = 0; np < 4; np++) {
                int nrow = wn * 64 + np * 16 + (lane >> 4) * 8 + (lane & 7);
                int kcol = khalf + ((lane >> 3) & 1) * 8;
                uint32_t off = (uint32_t)(nrow * SPITCH + kcol) * 2;
                uint32_t bh[4];
                ldm_x4(bh[0], bh[1], bh[2], bh[3], stB + off);
#pragma unroll
                for (int ms = 0; ms < 2; ms++)
#pragma unroll
                    for (int q = 0; q < 2; q++)
                        mma_f16(acc[ms][np * 2 + q], ah[ms], bh[2 * q], bh[2 * q + 1]);
            }
        }
        if (hasNext) STORE_A((kt + 1) & 1);
        __syncthreads();
    }
#undef FILL_B
#undef STORE_A
#undef LOAD_A

    // epilogue (unscale by 1/256, then optional bias+lrelu)
    const int rbase = by * 128 + wm * 32;
    const int cbase = bx * 128 + wn * 64;
    const int rq = lane >> 2, cq = (lane & 3) * 2;
#pragma unroll
    for (int ms = 0; ms < 2; ms++)
#pragma unroll
        for (int ns = 0; ns < 8; ns++) {
            int r0  = rbase + ms * 16 + rq;
            int col = cbase + ns * 8 + cq;
            float v0 = acc[ms][ns][0] * WSCALE_I, v1 = acc[ms][ns][1] * WSCALE_I;
            float v2 = acc[ms][ns][2] * WSCALE_I, v3 = acc[ms][ns][3] * WSCALE_I;
            if (EPI) {
                float b0 = bias[col], b1 = bias[col + 1];
                v0 = lrelu(v0 + b0); v1 = lrelu(v1 + b1);
                v2 = lrelu(v2 + b0); v3 = lrelu(v3 + b1);
            }
            *(float2*)&C[(size_t)r0 * NTOT + col]       = make_float2(v0, v1);
            *(float2*)&C[(size_t)(r0 + 8) * NTOT + col] = make_float2(v2, v3);
        }
}

// ------------------------- correlation kernel (smem-staged) ------------------
__global__ __launch_bounds__(256) void corr_kernel(const float* __restrict__ h,
                                                   float* __restrict__ corr_out) {
    extern __shared__ float4 hs4[];      // 14 rows x 256 float4 = 57344 B
    __shared__ float rn[14];
    __shared__ float cmat[196];
    __shared__ float dd[14];

    const int b = blockIdx.x;
    const int tid = threadIdx.x, lane = tid & 31, warp = tid >> 5;
    const float4* hb4 = (const float4*)(h + (size_t)b * 14336);

#pragma unroll
    for (int q = 0; q < 14; q++) hs4[tid + q * 256] = hb4[tid + q * 256];
    __syncthreads();

#pragma unroll 1
    for (int pass = 0; pass < 2; pass++) {
        int i = pass * 8 + warp;
        if (i < 14) {
            float4 ri[8];
#pragma unroll
            for (int k = 0; k < 8; k++) ri[k] = hs4[i * 256 + lane + 32 * k];
            float s = 0.f;
#pragma unroll
            for (int k = 0; k < 8; k++) {
                s = fmaf(ri[k].x, ri[k].x, s);
                s = fmaf(ri[k].y, ri[k].y, s);
                s = fmaf(ri[k].z, ri[k].z, s);
                s = fmaf(ri[k].w, ri[k].w, s);
            }
            s = wred(s);
            if (!lane) rn[i] = rsqrtf(fmaxf(s, 1e-16f));
#pragma unroll 1
            for (int j = i + 1; j < 14; j++) {
                float sj = 0.f;
#pragma unroll
                for (int k = 0; k < 8; k++) {
                    float4 vj = hs4[j * 256 + lane + 32 * k];
                    sj = fmaf(ri[k].x, vj.x, sj);
                    sj = fmaf(ri[k].y, vj.y, sj);
                    sj = fmaf(ri[k].z, vj.z, sj);
                    sj = fmaf(ri[k].w, vj.w, sj);
                }
                sj = wred(sj);
                if (!lane) cmat[i * 14 + j] = sj;
            }
        }
    }
    __syncthreads();

    float val = 0.f;
    if (tid < 196) {
        int i = tid / 14, j = tid % 14;
        if (i == j) val = 1.f;
        else {
            int lo = i < j ? i : j, hi = i < j ? j : i;
            val = fabsf(cmat[lo * 14 + hi] * rn[i] * rn[j]);
        }
    }
    __syncthreads();
    if (tid < 196) cmat[tid] = val;
    __syncthreads();
    if (tid < 14) {
        float s = 0.f;
        for (int j = 0; j < 14; j++) s += cmat[tid * 14 + j];
        dd[tid] = 1.f / sqrtf(fmaxf(s, 1.f));
    }
    __syncthreads();
    if (tid < 196) {
        int i = tid / 14, j = tid % 14;
        corr_out[(size_t)b * 196 + tid] = cmat[tid];
        g_corrn[(size_t)b * 196 + tid] = dd[i] * cmat[tid] * dd[j];
    }
}

// ------------------------- branch-1 aggregation + BN stats + fused reduce ----
__global__ __launch_bounds__(128) void agg1_kernel(
    const float* __restrict__ b1,
    const float* __restrict__ gamma1, const float* __restrict__ beta1,
    const float* __restrict__ gamma3, const float* __restrict__ beta3) {
    const int b = blockIdx.x, tid = threadIdx.x, lane = tid & 31, warp = tid >> 5;
    __shared__ __align__(8) float sh[14 * 512];
    __shared__ float sA1[196], sA2[196];
    __shared__ float red[4][14][4];
    __shared__ bool isLast;
    for (int t = tid; t < 196; t += 128) { sA1[t] = g_A1n[t]; sA2[t] = g_A2n[t]; }
    const float4* src = (const float4*)(g_xw1 + (size_t)b * 7168);
    float4* d4 = (float4*)sh;
#pragma unroll
    for (int k = 0; k < 14; k++) d4[tid + k * 128] = src[tid + k * 128];
    __syncthreads();
    float biasv[4];
#pragma unroll
    for (int t = 0; t < 4; t++) biasv[t] = b1[tid + t * 128];
    __half* p1 = g_pre16 + (size_t)b * 7168;
    __half* p3 = g_pre16 + (size_t)MROWS * 512 + (size_t)b * 7168;
#pragma unroll 1
    for (int i = 0; i < 14; i++) {
        float w1[14], w2[14];
#pragma unroll
        for (int j = 0; j < 14; j++) { w1[j] = sA1[i * 14 + j]; w2[j] = sA2[i * 14 + j]; }
        float s1 = 0, q1 = 0, s3 = 0, q3 = 0;
#pragma unroll
        for (int t = 0; t < 4; t++) {
            int c = tid + t * 128;
            float a1 = biasv[t], a3 = biasv[t];
#pragma unroll
            for (int j = 0; j < 14; j++) {
                float v = sh[j * 512 + c];
                a1 = fmaf(w1[j], v, a1);
                a3 = fmaf(w2[j], v, a3);
            }
            p1[i * 512 + c] = __float2half(a1);
            p3[i * 512 + c] = __float2half(a3);
            s1 += a1; q1 = fmaf(a1, a1, q1);
            s3 += a3; q3 = fmaf(a3, a3, q3);
        }
        s1 = wred(s1); q1 = wred(q1); s3 = wred(s3); q3 = wred(q3);
        if (!lane) { red[0][i][warp] = s1; red[1][i][warp] = q1; red[2][i][warp] = s3; red[3][i][warp] = q3; }
    }
    __syncthreads();
    if (tid < 28) {
        int node = tid % 14, st = tid / 14;
        double v1 = (double)red[st][node][0] + red[st][node][1] + red[st][node][2] + red[st][node][3];
        double v3 = (double)red[st + 2][node][0] + red[st + 2][node][1] + red[st + 2][node][2] + red[st + 2][node][3];
        g_part[(((size_t)0 * BATCH + b) * 14 + node) * 2 + st] = v1;
        g_part[(((size_t)1 * BATCH + b) * 14 + node) * 2 + st] = v3;
    }

    __threadfence();
    __syncthreads();
    if (tid == 0) {
        unsigned v = atomicAdd(&g_cnt1, 1u);
        isLast = (v == BATCH - 1);
        if (isLast) g_cnt1 = 0;
    }
    __syncthreads();
    if (isLast) {
        bn_finalize((double*)sh, 128, tid, 0, 1, gamma1, beta1, gamma3, beta3,
                    1.0 / ((double)BATCH * HID));
    }
}

// ------------------------- branch-2 aggregation (stats / write) --------------
template <bool WRITE>
__global__ __launch_bounds__(256) void agg2_kernel(
    const float* __restrict__ b2,
    const float* __restrict__ gamma2, const float* __restrict__ beta2,
    float* __restrict__ out) {
    const int b = blockIdx.x, tid = threadIdx.x, lane = tid & 31, warp = tid >> 5;
    __shared__ float sadj[196];
    __shared__ float sscale[2][14], sshift[2][14];
    __shared__ float red[4][14][8];
    __shared__ __align__(8) double chunk2[56 * 32];
    __shared__ bool isLast;
    if (tid < 196) sadj[tid] = g_corrn[(size_t)b * 196 + tid];
    if (WRITE && tid < 28) {
        int s = tid / 14, n = tid % 14;
        sscale[s][n] = g_scale[2 + s][n];
        sshift[s][n] = g_shift[2 + s][n];
    }
    __syncthreads();
    const float* xb = g_xw2 + (size_t)b * 14336;
    const float* xa = g_xw2 + (size_t)MROWS * 1024 + (size_t)b * 14336;

    float s2a[14], q2a[14], s4a[14], q4a[14];
    if (!WRITE) {
#pragma unroll
        for (int i = 0; i < 14; i++) { s2a[i] = 0; q2a[i] = 0; s4a[i] = 0; q4a[i] = 0; }
    }

#pragma unroll 1
    for (int t = 0; t < 4; t++) {
        const int c = tid + t * 256;
        float v2r[14], v4r[14];
#pragma unroll
        for (int j = 0; j < 14; j++) {
            v2r[j] = __ldg(xb + j * 1024 + c);
            v4r[j] = __ldg(xa + j * 1024 + c);
        }
        const float bv = __ldg(b2 + c);
#pragma unroll
        for (int i = 0; i < 14; i++) {
            float a2 = bv, a4 = bv;
#pragma unroll
            for (int j = 0; j < 14; j++) {
                float w = sadj[i * 14 + j];
                a2 = fmaf(w, v2r[j], a2);
                a4 = fmaf(w, v4r[j], a4);
            }
            if (WRITE) {
                out[((size_t)b * 14 + i) * 1024 + c] =
                    lrelu(fmaf(a2, sscale[0][i], sshift[0][i])) +
                    lrelu(fmaf(a4, sscale[1][i], sshift[1][i]));
            } else {
                s2a[i] += a2; q2a[i] = fmaf(a2, a2, q2a[i]);
                s4a[i] += a4; q4a[i] = fmaf(a4, a4, q4a[i]);
            }
        }
    }

    if (!WRITE) {
#pragma unroll 1
        for (int i = 0; i < 14; i++) {
            float s2 = wred(s2a[i]), q2 = wred(q2a[i]);
            float s4 = wred(s4a[i]), q4 = wred(q4a[i]);
            if (!lane) { red[0][i][warp] = s2; red[1][i][warp] = q2; red[2][i][warp] = s4; red[3][i][warp] = q4; }
        }
        __syncthreads();
        if (tid < 28) {
            int node = tid % 14, st = tid / 14;
            double v2 = 0, v4 = 0;
#pragma unroll
            for (int wq = 0; wq < 8; wq++) {
                v2 += (double)red[st][node][wq];
                v4 += (double)red[st + 2][node][wq];
            }
            g_part[(((size_t)2 * BATCH + b) * 14 + node) * 2 + st] = v2;
            g_part[(((size_t)3 * BATCH + b) * 14 + node) * 2 + st] = v4;
        }

        __threadfence();
        __syncthreads();
        if (tid == 0) {
            unsigned v = atomicAdd(&g_cnt2, 1u);
            isLast = (v == BATCH - 1);
            if (isLast) g_cnt2 = 0;
        }
        __syncthreads();
        if (isLast) {
            bn_finalize(chunk2, 256, tid, 2, 3, gamma2, beta2, gamma2, beta2,
                        1.0 / ((double)BATCH * FOUT));
        }
    }
}

// ------------------------- host launcher -------------------------------------
static void* sym_addr(const void* sym) {
    void* p = nullptr;
    cudaGetSymbolAddress(&p, sym);
    return p;
}

extern "C" void kernel_launch(void* const* d_in, const int* in_sizes, int n_in,
                              void* d_out, int out_size) {
    const float* x     = (const float*)d_in[0];
    const float* adj1  = (const float*)d_in[1];
    const float* adj2  = (const float*)d_in[2];
    const float* fc_w  = (const float*)d_in[3];
    const float* fc_b  = (const float*)d_in[4];
    const float* g1w   = (const float*)d_in[5];
    const float* g1b   = (const float*)d_in[6];
    const float* g2w   = (const float*)d_in[7];
    const float* g2b   = (const float*)d_in[8];
    const float* gamma1 = (const float*)d_in[9];
    const float* beta1  = (const float*)d_in[10];
    const float* gamma2 = (const float*)d_in[11];
    const float* beta2  = (const float*)d_in[12];
    const float* gamma3 = (const float*)d_in[13];
    const float* beta3  = (const float*)d_in[14];

    float* out      = (float*)d_out;
    float* corr_out = out + OFF_CORR;
    float* h_out    = out + OFF_H;

    __half* p_wfch  = (__half*)sym_addr(g_wfc_h);
    __half* p_w1h   = (__half*)sym_addr(g_w1_h);
    __half* p_w2h   = (__half*)sym_addr(g_w2_h);
    __half* p_pre16 = (__half*)sym_addr(g_pre16);
    float*  p_xw1   = (float*)sym_addr(g_xw1);
    float*  p_xw2   = (float*)sym_addr(g_xw2);

    const int CORR_SM = 14 * 1024 * 4;       // 57344

    static cudaStream_t s1 = nullptr;
    static cudaEvent_t eFork = nullptr, eJoin = nullptr;
    if (!s1) {
        cudaStreamCreateWithFlags(&s1, cudaStreamNonBlocking);
        cudaEventCreateWithFlags(&eFork, cudaEventDisableTiming);
        cudaEventCreateWithFlags(&eJoin, cudaEventDisableTiming);
        cudaFuncSetAttribute(hgemm2_k<1024, 1024, false, true,  false, false>, cudaFuncAttributeMaxDynamicSharedMemorySize, SM1);
        cudaFuncSetAttribute(hgemm2_k<1024,  512, false, false, false, false>, cudaFuncAttributeMaxDynamicSharedMemorySize, SM1);
        cudaFuncSetAttribute(hgemm2_k< 512, 1024, true,  false, true,  true >, cudaFuncAttributeMaxDynamicSharedMemorySize, SM1);
        cudaFuncSetAttribute(corr_kernel, cudaFuncAttributeMaxDynamicSharedMemorySize, CORR_SM);
    }

    // 1) fused prep: all weight splits + adjacency normalize
    prep_all<<<8193, 256>>>(fc_w, g1w, g2w, adj1, adj2);

    // ---- fork: chain A (fc GEMM -> corr) on s1 ----
    cudaEventRecord(eFork, 0);
    cudaStreamWaitEvent(s1, eFork, 0);

    hgemm2_k<1024, 1024, false, true, false, false><<<dim3(8, 448), 256, SM1, s1>>>(x, p_wfch, fc_b, h_out, 0);
    corr_kernel<<<BATCH, 256, CORR_SM, s1>>>(h_out, corr_out);
    cudaEventRecord(eJoin, s1);

    // ---- chain B (gcn1 -> agg1(+bn1) -> gcn2) on the main stream ----
    hgemm2_k<1024, 512, false, false, false, false><<<dim3(4, 448), 256, SM1>>>(x, p_w1h, nullptr, p_xw1, 0);
    agg1_kernel<<<BATCH, 128>>>(g1b, gamma1, beta1, gamma3, beta3);

    // stacked gcn2 GEMM: by<448 -> pre1/preset0, by>=448 -> pre3/preset1 (A fp16)
    hgemm2_k<512, 1024, true, false, true, true><<<dim3(8, 896), 256, SM1>>>(p_pre16, p_w2h, nullptr, p_xw2, 0);

    // ---- join: agg2 needs corrn (chain A) + xw2 (chain B) ----
    cudaStreamWaitEvent(0, eJoin, 0);

    agg2_kernel<false><<<BATCH, 256>>>(g2b, gamma2, beta2, nullptr);
    agg2_kernel<true><<<BATCH, 256>>>(g2b, gamma2, beta2, out);

    (void)in_sizes; (void)n_in; (void)out_size;
}